// round 14
// baseline (speedup 1.0000x reference)
#include <cuda_runtime.h>
#include <math.h>

#define N_SAMP 60000
#define NB1    118            // outer iterations
#define STRIDE 512            // n = STRIDE*n1 + 2*tid + {0,1}
#define N_PAD  (NB1 * STRIDE) // 60416, zero-padded tail
#define K_BINS 1400
#define BT     256
#define GRID_PSD (K_BINS / 2) // 700 blocks, 2 bins each

// Scratch (no allocations allowed).
// One float4 per n-group g (covers n = 2g, 2g+1): [x(2g), x(2g+1), y(2g), y(2g+1)]
__device__ float4   g_oxy4[N_PAD / 2];
__device__ float4   g_ri[K_BINS];   // (re1, im1, re2, im2)
__device__ unsigned g_ctr = 0;

// ---------------- packed f32x2 helpers (Blackwell native) ----------------
typedef unsigned long long ull;
__device__ __forceinline__ ull pk(float lo, float hi) {
    ull r; asm("mov.b64 %0,{%1,%2};" : "=l"(r) : "f"(lo), "f"(hi)); return r;
}
__device__ __forceinline__ void upk(ull v, float& lo, float& hi) {
    asm("mov.b64 {%0,%1},%2;" : "=f"(lo), "=f"(hi) : "l"(v));
}
__device__ __forceinline__ ull fma2(ull a, ull b, ull c) {
    ull d; asm("fma.rn.f32x2 %0,%1,%2,%3;" : "=l"(d) : "l"(a), "l"(b), "l"(c)); return d;
}
__device__ __forceinline__ ull mul2(ull a, ull b) {
    ull d; asm("mul.rn.f32x2 %0,%1,%2;" : "=l"(d) : "l"(a), "l"(b)); return d;
}
__device__ __forceinline__ ull add2(ull a, ull b) {
    ull d; asm("add.rn.f32x2 %0,%1,%2;" : "=l"(d) : "l"(a), "l"(b)); return d;
}
__device__ __forceinline__ ull neg2(ull a) {   // 2x LOP on alu pipe
    return a ^ 0x8000000080000000ULL;
}

// ---------------------------------------------------------------------------
// Kernel A: windowed signals into interleaved pair layout.
// Hann via cospif (accurate single-precision cos(pi*x)); symmetry halves
// the evals. Validated: shifts final rel_err by <1e-6 only.
// ---------------------------------------------------------------------------
__device__ __forceinline__ void store_oxy(int i, float x, float y) {
    float* base = (float*)g_oxy4;
    int g = i >> 1, q = i & 1;
    base[4 * g + q]     = x;
    base[4 * g + 2 + q] = y;
}

__global__ void prep_kernel(const float* __restrict__ preds,
                            const float* __restrict__ labels) {
    int i = blockIdx.x * blockDim.x + threadIdx.x;
    if (i < (N_PAD - N_SAMP)) store_oxy(N_SAMP + i, 0.f, 0.f);
    if (i >= N_SAMP / 2) return;
    // numpy: 0.5 - 0.5*cos(2*pi*i/(M-1)) == 0.5 + 0.5*cos(pi*(2i+1-M)/(M-1))
    float arg = (float)((double)(2 * i + 1 - N_SAMP) / (double)(N_SAMP - 1));
    float h = 0.5f + 0.5f * cospif(arg);
    store_oxy(i, preds[i] * h, labels[i] * h);
    int m = N_SAMP - 1 - i;
    store_oxy(m, preds[m] * h, labels[m] * h);
}

// ---------------------------------------------------------------------------
// Kernel B (R13 core + unroll 4): 2 bins per block, 2 consecutive n per
// lane (packed across n). Bitwise-identical per-term math:
//   tpn = RN(cF*n); e1,e2 exact FMA residuals; D = RN(k*e1+e2); ang = A - D
//   cos/sin(A) via table angle addition; first-order rotation by D.
// 29 fma2/iter = the audited op floor for bit-matching the reference.
// Unroll 4 supplies independent chains to cover LDS/FMA latency.
// Last block (atomic counter) computes the final scalar inline.
// ---------------------------------------------------------------------------
__global__ void __launch_bounds__(BT, 5)
psd_kernel(const float* __restrict__ bpm, float* __restrict__ out) {
    const int j0  = blockIdx.x * 2;
    const int tid = threadIdx.x;

    __shared__ float4 tb1[2][NB1];    // per bin: (cB, cB, -sB, -sB)
    __shared__ float2 tb2[2][NB1];    // per bin: (sB, sB)
    __shared__ float4 wsum[8][2];
    // final-phase storage (only last block uses)
    __shared__ float  ca1s[K_BINS];
    __shared__ float  ca2s[K_BINS];
    __shared__ float  redf[64];
    __shared__ double redd[8];
    __shared__ unsigned done;

    const float cF   = (float)(2.0 * 3.141592653589793 / 60000.0);
    const float unit = (float)(30.0 / 60000.0);

    float  kk[2];
    double kc[2];
#pragma unroll
    for (int b = 0; b < 2; b++) {
        kk[b] = __fdiv_rn(__fdiv_rn(bpm[j0 + b], 60.0f), unit);
        kc[b] = (double)kk[b] * (double)cF;        // exact product in fp64
    }
    ull k2[2], nk2[2];
#pragma unroll
    for (int b = 0; b < 2; b++) {
        k2[b]  = pk(kk[b], kk[b]);
        nk2[b] = neg2(k2[b]);
    }

    // Block tables: cos/sin(k*cF*STRIDE*n1)
    for (int idx = tid; idx < 2 * NB1; idx += BT) {
        int b = (idx >= NB1) ? 1 : 0;
        int n1 = idx - b * NB1;
        double s, c;
        sincos(kc[b] * (double)(n1 * STRIDE), &s, &c);
        tb1[b][n1] = make_float4((float)c, (float)c, (float)(-s), (float)(-s));
        tb2[b][n1] = make_float2((float)s, (float)s);
    }

    // Per-thread inner factors: cos/sin(k*cF*(2*tid+q)), q in {0,1}
    ull cS2[2], sS2[2];
#pragma unroll
    for (int b = 0; b < 2; b++) {
        double s0, c0, s1, c1;
        sincos(kc[b] * (double)(2 * tid),     &s0, &c0);
        sincos(kc[b] * (double)(2 * tid + 1), &s1, &c1);
        cS2[b] = pk((float)c0, (float)c1);
        sS2[b] = pk((float)s0, (float)s1);
    }
    __syncthreads();

    // Main loop
    const ull cF2  = pk(cF, cF);
    const ull stp2 = pk((float)STRIDE, (float)STRIDE);
    ull nf2 = pk((float)(2 * tid), (float)(2 * tid + 1));  // exact ints in f32
    ull aR[2] = {0ULL, 0ULL}, aI[2] = {0ULL, 0ULL};
    ull bR[2] = {0ULL, 0ULL}, bI[2] = {0ULL, 0ULL};
    const ulonglong2* p = (const ulonglong2*)g_oxy4 + tid;  // 16B per group

#pragma unroll 4
    for (int n1 = 0; n1 < NB1; ++n1) {
        // shared chain (both bins): reference rounding + exact residual
        ull tpn2 = mul2(cF2, nf2);               // RN(cF*n) per lane
        ull e1   = fma2(cF2, nf2, neg2(tpn2));   // exact: cF*n - tpn
        nf2 = add2(nf2, stp2);
        ulonglong2 o = p[n1 * BT];               // LDG.128: (x,x',y,y')
        ull ox2 = o.x;
        ull oy2 = o.y;
#pragma unroll
        for (int b = 0; b < 2; b++) {
            float4 t1 = tb1[b][n1];              // LDS.128
            float2 t2 = tb2[b][n1];              // LDS.64
            ull cB2  = pk(t1.x, t1.y);
            ull nsB2 = pk(t1.z, t1.w);
            ull sB2  = pk(t2.x, t2.y);
            ull ang  = mul2(k2[b], tpn2);        // RN(k*tpn)
            ull ne2  = fma2(nk2[b], tpn2, ang);  // exact: -(k*tpn - ang) = -e2
            ull nD   = fma2(nk2[b], e1, ne2);    // exact negation: -D
            ull D    = neg2(nD);                 // ALU pipe (the only per-bin neg)
            ull cA   = fma2(nsB2, sS2[b], mul2(cB2, cS2[b]));
            ull sA   = fma2(cB2, sS2[b], mul2(sB2, cS2[b]));
            ull cr   = fma2(D, sA, cA);          // cos(A - D), 1st order
            ull sr   = fma2(nD, cA, sA);         // sin(A - D), 1st order
            aR[b] = fma2(cr, ox2, aR[b]);
            aI[b] = fma2(sr, ox2, aI[b]);
            bR[b] = fma2(cr, oy2, bR[b]);
            bI[b] = fma2(sr, oy2, bI[b]);
        }
    }

    // Reduce: combine packed halves, then warp/block tree (8 scalars)
    float r1[2], i1[2], r2[2], i2[2];
#pragma unroll
    for (int b = 0; b < 2; b++) {
        float lo, hi;
        upk(aR[b], lo, hi); r1[b] = lo + hi;
        upk(aI[b], lo, hi); i1[b] = lo + hi;
        upk(bR[b], lo, hi); r2[b] = lo + hi;
        upk(bI[b], lo, hi); i2[b] = lo + hi;
    }
    const unsigned msk = 0xFFFFFFFFu;
    for (int off = 16; off; off >>= 1) {
#pragma unroll
        for (int b = 0; b < 2; b++) {
            r1[b] += __shfl_down_sync(msk, r1[b], off);
            i1[b] += __shfl_down_sync(msk, i1[b], off);
            r2[b] += __shfl_down_sync(msk, r2[b], off);
            i2[b] += __shfl_down_sync(msk, i2[b], off);
        }
    }
    int w = tid >> 5, lane = tid & 31;
    if (lane == 0) {
#pragma unroll
        for (int b = 0; b < 2; b++)
            wsum[w][b] = make_float4(r1[b], i1[b], r2[b], i2[b]);
    }
    __syncthreads();
    if (w == 0) {
#pragma unroll
        for (int b = 0; b < 2; b++) {
            float4 v = (lane < 8) ? wsum[lane][b] : make_float4(0.f, 0.f, 0.f, 0.f);
            for (int off = 4; off; off >>= 1) {
                v.x += __shfl_down_sync(msk, v.x, off);
                v.y += __shfl_down_sync(msk, v.y, off);
                v.z += __shfl_down_sync(msk, v.z, off);
                v.w += __shfl_down_sync(msk, v.w, off);
            }
            if (lane == 0) g_ri[j0 + b] = v;
        }
    }

    // ---- completion protocol: last block computes the final scalar ----
    __threadfence();
    if (tid == 0) done = atomicAdd(&g_ctr, 1);
    __syncthreads();
    if (done != GRID_PSD - 1) return;
    __threadfence();   // order: counter observation -> g_ri reads

    // Final reduction: pn = ca/max(ca); ||pn1-pn2||; 1/(l+eps)
    float m1 = 0.f, m2 = 0.f;
    for (int j = tid; j < K_BINS; j += BT) {
        float4 v = g_ri[j];
        float ca1 = __fmaf_rn(v.y, v.y, __fmul_rn(v.x, v.x));
        float ca2 = __fmaf_rn(v.w, v.w, __fmul_rn(v.z, v.z));
        ca1s[j] = ca1; ca2s[j] = ca2;
        m1 = fmaxf(m1, ca1); m2 = fmaxf(m2, ca2);
    }
    for (int off = 16; off; off >>= 1) {
        m1 = fmaxf(m1, __shfl_down_sync(msk, m1, off));
        m2 = fmaxf(m2, __shfl_down_sync(msk, m2, off));
    }
    if (lane == 0) { redf[w] = m1; redf[32 + w] = m2; }
    __syncthreads();
    if (tid == 0) {
        float a = redf[0], bb = redf[32];
        for (int i = 1; i < 8; i++) { a = fmaxf(a, redf[i]); bb = fmaxf(bb, redf[32 + i]); }
        redf[0] = a; redf[32] = bb;
    }
    __syncthreads();
    const float max1 = redf[0], max2 = redf[32];

    double ss = 0.0;
    for (int j = tid; j < K_BINS; j += BT) {
        float p1 = __fdiv_rn(ca1s[j], max1);
        float p2 = __fdiv_rn(ca2s[j], max2);
        double d = (double)p1 - (double)p2;
        ss += d * d;
    }
    for (int off = 16; off; off >>= 1) ss += __shfl_down_sync(msk, ss, off);
    if (lane == 0) redd[w] = ss;
    __syncthreads();
    if (tid == 0) {
        double t = 0.0;
        for (int i = 0; i < 8; i++) t += redd[i];
        float loss = (float)sqrt(t);
        out[0] = __fdiv_rn(1.0f, loss + 1e-8f);
        g_ctr = 0;     // reset for next graph replay
    }
}

// ---------------------------------------------------------------------------
// Inputs (metadata order): preds f32[60000], labels f32[60000], Fs i32[1],
//                          bpm_range f32[1400]. Output: f32[1].
// ---------------------------------------------------------------------------
extern "C" void kernel_launch(void* const* d_in, const int* in_sizes, int n_in,
                              void* d_out, int out_size) {
    const float* preds  = (const float*)d_in[0];
    const float* labels = (const float*)d_in[1];
    const float* bpm    = (const float*)d_in[3];

    prep_kernel<<<(N_SAMP / 2 + 255) / 256, 256>>>(preds, labels);
    psd_kernel<<<GRID_PSD, BT>>>(bpm, (float*)d_out);
}

// round 15
// speedup vs baseline: 1.0883x; 1.0883x over previous
#include <cuda_runtime.h>
#include <math.h>

#define N_SAMP 60000
#define NB1    118            // outer iterations
#define STRIDE 512            // n = STRIDE*n1 + 2*tid + {0,1}
#define N_PAD  (NB1 * STRIDE) // 60416, zero-padded tail
#define K_BINS 1400
#define BT     256
#define GRID_PSD (K_BINS / 2) // 700 blocks, 2 bins each; 700 <= 5*148 -> one wave

// Scratch (no allocations allowed).
// One float4 per n-group g (covers n = 2g, 2g+1): [x(2g), x(2g+1), y(2g), y(2g+1)]
__device__ float4   g_oxy4[N_PAD / 2];
__device__ float4   g_ri[K_BINS];   // (re1, im1, re2, im2)
__device__ unsigned g_ctr  = 0;     // completion counter (final reduction)
__device__ unsigned g_pctr = 0;     // prep-phase barrier counter

// ---------------- packed f32x2 helpers (Blackwell native) ----------------
typedef unsigned long long ull;
__device__ __forceinline__ ull pk(float lo, float hi) {
    ull r; asm("mov.b64 %0,{%1,%2};" : "=l"(r) : "f"(lo), "f"(hi)); return r;
}
__device__ __forceinline__ void upk(ull v, float& lo, float& hi) {
    asm("mov.b64 {%0,%1},%2;" : "=f"(lo), "=f"(hi) : "l"(v));
}
__device__ __forceinline__ ull fma2(ull a, ull b, ull c) {
    ull d; asm("fma.rn.f32x2 %0,%1,%2,%3;" : "=l"(d) : "l"(a), "l"(b), "l"(c)); return d;
}
__device__ __forceinline__ ull mul2(ull a, ull b) {
    ull d; asm("mul.rn.f32x2 %0,%1,%2;" : "=l"(d) : "l"(a), "l"(b)); return d;
}
__device__ __forceinline__ ull add2(ull a, ull b) {
    ull d; asm("add.rn.f32x2 %0,%1,%2;" : "=l"(d) : "l"(a), "l"(b)); return d;
}
__device__ __forceinline__ ull neg2(ull a) {   // 2x LOP on alu pipe
    return a ^ 0x8000000080000000ULL;
}

__device__ __forceinline__ void store_oxy(int i, float x, float y) {
    float* base = (float*)g_oxy4;
    int g = i >> 1, q = i & 1;
    base[4 * g + q]     = x;
    base[4 * g + 2 + q] = y;
}

// ---------------------------------------------------------------------------
// Fused kernel: prep phase (windowing) + grid barrier + PSD + final scalar.
// Entire 700-block grid is co-resident (5 blocks/SM x 148 SMs = 740), so the
// software grid barrier cannot deadlock. Counters are reset by the last
// finishing block (which runs strictly after every block passed the barrier).
// Per-term PSD math bitwise-identical to the R13-measured optimum:
//   tpn = RN(cF*n); e1,e2 exact FMA residuals; D = RN(k*e1+e2); ang = A - D
//   cos/sin(A) via table angle addition; first-order rotation by D.
// ---------------------------------------------------------------------------
__global__ void __launch_bounds__(BT, 5)
psd_kernel(const float* __restrict__ preds,
           const float* __restrict__ labels,
           const float* __restrict__ bpm,
           float* __restrict__ out) {
    const int j0  = blockIdx.x * 2;
    const int tid = threadIdx.x;
    const int t   = blockIdx.x * BT + tid;   // global thread id

    __shared__ float4 tb1[2][NB1];    // per bin: (cB, cB, -sB, -sB)
    __shared__ float2 tb2[2][NB1];    // per bin: (sB, sB)
    __shared__ float4 wsum[8][2];
    __shared__ float  ca1s[K_BINS];
    __shared__ float  ca2s[K_BINS];
    __shared__ float  redf[64];
    __shared__ double redd[8];
    __shared__ unsigned done;

    // ---- Phase 0: prep (windowed signals), spread across the whole grid ----
    if (t < (N_PAD - N_SAMP)) store_oxy(N_SAMP + t, 0.f, 0.f);
    if (t < N_SAMP / 2) {
        // numpy: 0.5 - 0.5*cos(2*pi*i/(M-1)) == 0.5 + 0.5*cos(pi*(2i+1-M)/(M-1))
        float arg = (float)((double)(2 * t + 1 - N_SAMP) / (double)(N_SAMP - 1));
        float h = 0.5f + 0.5f * cospif(arg);
        store_oxy(t, preds[t] * h, labels[t] * h);
        int m = N_SAMP - 1 - t;
        store_oxy(m, preds[m] * h, labels[m] * h);
    }
    __threadfence();            // publish prep stores
    __syncthreads();
    if (tid == 0) atomicAdd(&g_pctr, 1u);   // arrive (prep done for this block)

    // ---- Phase 1: per-block trig tables (overlaps other blocks' prep) ----
    const float cF   = (float)(2.0 * 3.141592653589793 / 60000.0);
    const float unit = (float)(30.0 / 60000.0);

    float  kk[2];
    double kc[2];
#pragma unroll
    for (int b = 0; b < 2; b++) {
        kk[b] = __fdiv_rn(__fdiv_rn(bpm[j0 + b], 60.0f), unit);
        kc[b] = (double)kk[b] * (double)cF;        // exact product in fp64
    }
    ull k2[2], nk2[2];
#pragma unroll
    for (int b = 0; b < 2; b++) {
        k2[b]  = pk(kk[b], kk[b]);
        nk2[b] = neg2(k2[b]);
    }

    for (int idx = tid; idx < 2 * NB1; idx += BT) {
        int b = (idx >= NB1) ? 1 : 0;
        int n1 = idx - b * NB1;
        double s, c;
        sincos(kc[b] * (double)(n1 * STRIDE), &s, &c);
        tb1[b][n1] = make_float4((float)c, (float)c, (float)(-s), (float)(-s));
        tb2[b][n1] = make_float2((float)s, (float)s);
    }

    ull cS2[2], sS2[2];
#pragma unroll
    for (int b = 0; b < 2; b++) {
        double s0, c0, s1, c1;
        sincos(kc[b] * (double)(2 * tid),     &s0, &c0);
        sincos(kc[b] * (double)(2 * tid + 1), &s1, &c1);
        cS2[b] = pk((float)c0, (float)c1);
        sS2[b] = pk((float)s0, (float)s1);
    }
    __syncthreads();

    // ---- Grid barrier: wait until every block's prep stores are visible ----
    if (tid == 0) {
        while (atomicAdd(&g_pctr, 0u) < (unsigned)GRID_PSD) __nanosleep(64);
    }
    __syncthreads();
    __threadfence();            // acquire: ordered before g_oxy4 reads

    // ---- Phase 2: main loop (R13-measured optimum, unroll 2) ----
    const ull cF2  = pk(cF, cF);
    const ull stp2 = pk((float)STRIDE, (float)STRIDE);
    ull nf2 = pk((float)(2 * tid), (float)(2 * tid + 1));  // exact ints in f32
    ull aR[2] = {0ULL, 0ULL}, aI[2] = {0ULL, 0ULL};
    ull bR[2] = {0ULL, 0ULL}, bI[2] = {0ULL, 0ULL};
    const ulonglong2* p = (const ulonglong2*)g_oxy4 + tid;  // 16B per group

#pragma unroll 2
    for (int n1 = 0; n1 < NB1; ++n1) {
        // shared chain (both bins): reference rounding + exact residual
        ull tpn2 = mul2(cF2, nf2);               // RN(cF*n) per lane
        ull e1   = fma2(cF2, nf2, neg2(tpn2));   // exact: cF*n - tpn
        nf2 = add2(nf2, stp2);
        ulonglong2 o = p[n1 * BT];               // LDG.128: (x,x',y,y')
        ull ox2 = o.x;
        ull oy2 = o.y;
#pragma unroll
        for (int b = 0; b < 2; b++) {
            float4 t1 = tb1[b][n1];              // LDS.128
            float2 t2 = tb2[b][n1];              // LDS.64
            ull cB2  = pk(t1.x, t1.y);
            ull nsB2 = pk(t1.z, t1.w);
            ull sB2  = pk(t2.x, t2.y);
            ull ang  = mul2(k2[b], tpn2);        // RN(k*tpn)
            ull ne2  = fma2(nk2[b], tpn2, ang);  // exact: -(k*tpn - ang) = -e2
            ull nD   = fma2(nk2[b], e1, ne2);    // exact negation: -D
            ull D    = neg2(nD);                 // ALU pipe (the only per-bin neg)
            ull cA   = fma2(nsB2, sS2[b], mul2(cB2, cS2[b]));
            ull sA   = fma2(cB2, sS2[b], mul2(sB2, cS2[b]));
            ull cr   = fma2(D, sA, cA);          // cos(A - D), 1st order
            ull sr   = fma2(nD, cA, sA);         // sin(A - D), 1st order
            aR[b] = fma2(cr, ox2, aR[b]);
            aI[b] = fma2(sr, ox2, aI[b]);
            bR[b] = fma2(cr, oy2, bR[b]);
            bI[b] = fma2(sr, oy2, bI[b]);
        }
    }

    // Reduce: combine packed halves, then warp/block tree (8 scalars)
    float r1[2], i1[2], r2[2], i2[2];
#pragma unroll
    for (int b = 0; b < 2; b++) {
        float lo, hi;
        upk(aR[b], lo, hi); r1[b] = lo + hi;
        upk(aI[b], lo, hi); i1[b] = lo + hi;
        upk(bR[b], lo, hi); r2[b] = lo + hi;
        upk(bI[b], lo, hi); i2[b] = lo + hi;
    }
    const unsigned msk = 0xFFFFFFFFu;
    for (int off = 16; off; off >>= 1) {
#pragma unroll
        for (int b = 0; b < 2; b++) {
            r1[b] += __shfl_down_sync(msk, r1[b], off);
            i1[b] += __shfl_down_sync(msk, i1[b], off);
            r2[b] += __shfl_down_sync(msk, r2[b], off);
            i2[b] += __shfl_down_sync(msk, i2[b], off);
        }
    }
    int w = tid >> 5, lane = tid & 31;
    if (lane == 0) {
#pragma unroll
        for (int b = 0; b < 2; b++)
            wsum[w][b] = make_float4(r1[b], i1[b], r2[b], i2[b]);
    }
    __syncthreads();
    if (w == 0) {
#pragma unroll
        for (int b = 0; b < 2; b++) {
            float4 v = (lane < 8) ? wsum[lane][b] : make_float4(0.f, 0.f, 0.f, 0.f);
            for (int off = 4; off; off >>= 1) {
                v.x += __shfl_down_sync(msk, v.x, off);
                v.y += __shfl_down_sync(msk, v.y, off);
                v.z += __shfl_down_sync(msk, v.z, off);
                v.w += __shfl_down_sync(msk, v.w, off);
            }
            if (lane == 0) g_ri[j0 + b] = v;
        }
    }

    // ---- completion protocol: last block computes the final scalar ----
    __threadfence();
    if (tid == 0) done = atomicAdd(&g_ctr, 1);
    __syncthreads();
    if (done != GRID_PSD - 1) return;
    __threadfence();   // order: counter observation -> g_ri reads

    // Final reduction: pn = ca/max(ca); ||pn1-pn2||; 1/(l+eps)
    float m1 = 0.f, m2 = 0.f;
    for (int j = tid; j < K_BINS; j += BT) {
        float4 v = g_ri[j];
        float ca1 = __fmaf_rn(v.y, v.y, __fmul_rn(v.x, v.x));
        float ca2 = __fmaf_rn(v.w, v.w, __fmul_rn(v.z, v.z));
        ca1s[j] = ca1; ca2s[j] = ca2;
        m1 = fmaxf(m1, ca1); m2 = fmaxf(m2, ca2);
    }
    for (int off = 16; off; off >>= 1) {
        m1 = fmaxf(m1, __shfl_down_sync(msk, m1, off));
        m2 = fmaxf(m2, __shfl_down_sync(msk, m2, off));
    }
    if (lane == 0) { redf[w] = m1; redf[32 + w] = m2; }
    __syncthreads();
    if (tid == 0) {
        float a = redf[0], bb = redf[32];
        for (int i = 1; i < 8; i++) { a = fmaxf(a, redf[i]); bb = fmaxf(bb, redf[32 + i]); }
        redf[0] = a; redf[32] = bb;
    }
    __syncthreads();
    const float max1 = redf[0], max2 = redf[32];

    double ss = 0.0;
    for (int j = tid; j < K_BINS; j += BT) {
        float p1 = __fdiv_rn(ca1s[j], max1);
        float p2 = __fdiv_rn(ca2s[j], max2);
        double d = (double)p1 - (double)p2;
        ss += d * d;
    }
    for (int off = 16; off; off >>= 1) ss += __shfl_down_sync(msk, ss, off);
    if (lane == 0) redd[w] = ss;
    __syncthreads();
    if (tid == 0) {
        double tt = 0.0;
        for (int i = 0; i < 8; i++) tt += redd[i];
        float loss = (float)sqrt(tt);
        out[0] = __fdiv_rn(1.0f, loss + 1e-8f);
        g_ctr  = 0;    // reset for next graph replay
        g_pctr = 0;    // (runs after every block passed the prep barrier)
    }
}

// ---------------------------------------------------------------------------
// Inputs (metadata order): preds f32[60000], labels f32[60000], Fs i32[1],
//                          bpm_range f32[1400]. Output: f32[1].
// ---------------------------------------------------------------------------
extern "C" void kernel_launch(void* const* d_in, const int* in_sizes, int n_in,
                              void* d_out, int out_size) {
    const float* preds  = (const float*)d_in[0];
    const float* labels = (const float*)d_in[1];
    const float* bpm    = (const float*)d_in[3];

    psd_kernel<<<GRID_PSD, BT>>>(preds, labels, bpm, (float*)d_out);
}

// round 16
// speedup vs baseline: 1.0888x; 1.0004x over previous
#include <cuda_runtime.h>
#include <math.h>

#define N_SAMP 60000
#define NB1    118            // outer iterations
#define STRIDE 512            // n = STRIDE*n1 + 2*tid + {0,1}
#define N_PAD  (NB1 * STRIDE) // 60416, zero-padded tail
#define K_BINS 1400
#define BT     256
#define GRID_PSD (K_BINS / 2) // 700 blocks, 2 bins each; 700 <= 5*148 -> one wave

// Scratch (no allocations allowed).
// One float4 per n-group g (covers n = 2g, 2g+1): [x(2g), x(2g+1), y(2g), y(2g+1)]
__device__ float4   g_oxy4[N_PAD / 2];
__device__ float4   g_ri[K_BINS];   // (re1, im1, re2, im2)
__device__ unsigned g_ctr  = 0;     // completion counter (final reduction)
__device__ unsigned g_pctr = 0;     // prep-phase barrier counter

// ---------------- packed f32x2 helpers (Blackwell native) ----------------
typedef unsigned long long ull;
__device__ __forceinline__ ull pk(float lo, float hi) {
    ull r; asm("mov.b64 %0,{%1,%2};" : "=l"(r) : "f"(lo), "f"(hi)); return r;
}
__device__ __forceinline__ void upk(ull v, float& lo, float& hi) {
    asm("mov.b64 {%0,%1},%2;" : "=f"(lo), "=f"(hi) : "l"(v));
}
__device__ __forceinline__ ull fma2(ull a, ull b, ull c) {
    ull d; asm("fma.rn.f32x2 %0,%1,%2,%3;" : "=l"(d) : "l"(a), "l"(b), "l"(c)); return d;
}
__device__ __forceinline__ ull mul2(ull a, ull b) {
    ull d; asm("mul.rn.f32x2 %0,%1,%2;" : "=l"(d) : "l"(a), "l"(b)); return d;
}
__device__ __forceinline__ ull add2(ull a, ull b) {
    ull d; asm("add.rn.f32x2 %0,%1,%2;" : "=l"(d) : "l"(a), "l"(b)); return d;
}
__device__ __forceinline__ ull neg2(ull a) {   // 2x LOP on alu pipe
    return a ^ 0x8000000080000000ULL;
}
__device__ __forceinline__ unsigned ld_acq(const unsigned* p) {
    unsigned v;
    asm volatile("ld.global.acquire.gpu.u32 %0, [%1];" : "=r"(v) : "l"(p) : "memory");
    return v;
}

__device__ __forceinline__ void store_oxy(int i, float x, float y) {
    float* base = (float*)g_oxy4;
    int g = i >> 1, q = i & 1;
    base[4 * g + q]     = x;
    base[4 * g + 2 + q] = y;
}

// ---------------------------------------------------------------------------
// Fused kernel: prep phase (windowing) + grid barrier + PSD + final scalar.
// Entire 700-block grid is co-resident (5 blocks/SM x 148 SMs = 740), so the
// software grid barrier cannot deadlock. Counters are reset by the last
// finishing block (strictly after every block passed the barrier).
// Per-term PSD math bitwise-identical to the R13-measured optimum:
//   tpn = RN(cF*n); e1,e2 exact FMA residuals; D = RN(k*e1+e2); ang = A - D
//   cos/sin(A) via table angle addition; first-order rotation by D.
// Barrier spin uses acquire-loads (no L2 atomic serialization among pollers).
// ---------------------------------------------------------------------------
__global__ void __launch_bounds__(BT, 5)
psd_kernel(const float* __restrict__ preds,
           const float* __restrict__ labels,
           const float* __restrict__ bpm,
           float* __restrict__ out) {
    const int j0  = blockIdx.x * 2;
    const int tid = threadIdx.x;
    const int t   = blockIdx.x * BT + tid;   // global thread id

    __shared__ float4 tb1[2][NB1];    // per bin: (cB, cB, -sB, -sB)
    __shared__ float2 tb2[2][NB1];    // per bin: (sB, sB)
    __shared__ float4 wsum[8][2];
    __shared__ float  ca1s[K_BINS];
    __shared__ float  ca2s[K_BINS];
    __shared__ float  redf[64];
    __shared__ double redd[8];
    __shared__ unsigned done;

    // ---- Phase 0: prep (windowed signals), spread across the whole grid ----
    if (t < (N_PAD - N_SAMP)) store_oxy(N_SAMP + t, 0.f, 0.f);
    if (t < N_SAMP / 2) {
        // numpy: 0.5 - 0.5*cos(2*pi*i/(M-1)) == 0.5 + 0.5*cos(pi*(2i+1-M)/(M-1))
        float arg = (float)((double)(2 * t + 1 - N_SAMP) / (double)(N_SAMP - 1));
        float h = 0.5f + 0.5f * cospif(arg);
        store_oxy(t, preds[t] * h, labels[t] * h);
        int m = N_SAMP - 1 - t;
        store_oxy(m, preds[m] * h, labels[m] * h);
    }
    __threadfence();            // publish prep stores
    __syncthreads();
    if (tid == 0) atomicAdd(&g_pctr, 1u);   // arrive (prep done for this block)

    // ---- Phase 1: per-block trig tables (overlaps other blocks' prep) ----
    const float cF   = (float)(2.0 * 3.141592653589793 / 60000.0);
    const float unit = (float)(30.0 / 60000.0);

    float  kk[2];
    double kc[2];
#pragma unroll
    for (int b = 0; b < 2; b++) {
        kk[b] = __fdiv_rn(__fdiv_rn(bpm[j0 + b], 60.0f), unit);
        kc[b] = (double)kk[b] * (double)cF;        // exact product in fp64
    }
    ull k2[2], nk2[2];
#pragma unroll
    for (int b = 0; b < 2; b++) {
        k2[b]  = pk(kk[b], kk[b]);
        nk2[b] = neg2(k2[b]);
    }

    for (int idx = tid; idx < 2 * NB1; idx += BT) {
        int b = (idx >= NB1) ? 1 : 0;
        int n1 = idx - b * NB1;
        double s, c;
        sincos(kc[b] * (double)(n1 * STRIDE), &s, &c);
        tb1[b][n1] = make_float4((float)c, (float)c, (float)(-s), (float)(-s));
        tb2[b][n1] = make_float2((float)s, (float)s);
    }

    ull cS2[2], sS2[2];
#pragma unroll
    for (int b = 0; b < 2; b++) {
        double s0, c0, s1, c1;
        sincos(kc[b] * (double)(2 * tid),     &s0, &c0);
        sincos(kc[b] * (double)(2 * tid + 1), &s1, &c1);
        cS2[b] = pk((float)c0, (float)c1);
        sS2[b] = pk((float)s0, (float)s1);
    }
    __syncthreads();

    // ---- Grid barrier: wait until every block's prep stores are visible ----
    if (tid == 0) {
        while (ld_acq(&g_pctr) < (unsigned)GRID_PSD) __nanosleep(32);
    }
    __syncthreads();
    __threadfence();            // acquire: ordered before g_oxy4 reads

    // ---- Phase 2: main loop (R13-measured optimum, unroll 2) ----
    const ull cF2  = pk(cF, cF);
    const ull stp2 = pk((float)STRIDE, (float)STRIDE);
    ull nf2 = pk((float)(2 * tid), (float)(2 * tid + 1));  // exact ints in f32
    ull aR[2] = {0ULL, 0ULL}, aI[2] = {0ULL, 0ULL};
    ull bR[2] = {0ULL, 0ULL}, bI[2] = {0ULL, 0ULL};
    const ulonglong2* p = (const ulonglong2*)g_oxy4 + tid;  // 16B per group

#pragma unroll 2
    for (int n1 = 0; n1 < NB1; ++n1) {
        // shared chain (both bins): reference rounding + exact residual
        ull tpn2 = mul2(cF2, nf2);               // RN(cF*n) per lane
        ull e1   = fma2(cF2, nf2, neg2(tpn2));   // exact: cF*n - tpn
        nf2 = add2(nf2, stp2);
        ulonglong2 o = p[n1 * BT];               // LDG.128: (x,x',y,y')
        ull ox2 = o.x;
        ull oy2 = o.y;
#pragma unroll
        for (int b = 0; b < 2; b++) {
            float4 t1 = tb1[b][n1];              // LDS.128
            float2 t2 = tb2[b][n1];              // LDS.64
            ull cB2  = pk(t1.x, t1.y);
            ull nsB2 = pk(t1.z, t1.w);
            ull sB2  = pk(t2.x, t2.y);
            ull ang  = mul2(k2[b], tpn2);        // RN(k*tpn)
            ull ne2  = fma2(nk2[b], tpn2, ang);  // exact: -(k*tpn - ang) = -e2
            ull nD   = fma2(nk2[b], e1, ne2);    // exact negation: -D
            ull D    = neg2(nD);                 // ALU pipe (the only per-bin neg)
            ull cA   = fma2(nsB2, sS2[b], mul2(cB2, cS2[b]));
            ull sA   = fma2(cB2, sS2[b], mul2(sB2, cS2[b]));
            ull cr   = fma2(D, sA, cA);          // cos(A - D), 1st order
            ull sr   = fma2(nD, cA, sA);         // sin(A - D), 1st order
            aR[b] = fma2(cr, ox2, aR[b]);
            aI[b] = fma2(sr, ox2, aI[b]);
            bR[b] = fma2(cr, oy2, bR[b]);
            bI[b] = fma2(sr, oy2, bI[b]);
        }
    }

    // Reduce: combine packed halves, then warp/block tree (8 scalars)
    float r1[2], i1[2], r2[2], i2[2];
#pragma unroll
    for (int b = 0; b < 2; b++) {
        float lo, hi;
        upk(aR[b], lo, hi); r1[b] = lo + hi;
        upk(aI[b], lo, hi); i1[b] = lo + hi;
        upk(bR[b], lo, hi); r2[b] = lo + hi;
        upk(bI[b], lo, hi); i2[b] = lo + hi;
    }
    const unsigned msk = 0xFFFFFFFFu;
    for (int off = 16; off; off >>= 1) {
#pragma unroll
        for (int b = 0; b < 2; b++) {
            r1[b] += __shfl_down_sync(msk, r1[b], off);
            i1[b] += __shfl_down_sync(msk, i1[b], off);
            r2[b] += __shfl_down_sync(msk, r2[b], off);
            i2[b] += __shfl_down_sync(msk, i2[b], off);
        }
    }
    int w = tid >> 5, lane = tid & 31;
    if (lane == 0) {
#pragma unroll
        for (int b = 0; b < 2; b++)
            wsum[w][b] = make_float4(r1[b], i1[b], r2[b], i2[b]);
    }
    __syncthreads();
    if (w == 0) {
#pragma unroll
        for (int b = 0; b < 2; b++) {
            float4 v = (lane < 8) ? wsum[lane][b] : make_float4(0.f, 0.f, 0.f, 0.f);
            for (int off = 4; off; off >>= 1) {
                v.x += __shfl_down_sync(msk, v.x, off);
                v.y += __shfl_down_sync(msk, v.y, off);
                v.z += __shfl_down_sync(msk, v.z, off);
                v.w += __shfl_down_sync(msk, v.w, off);
            }
            if (lane == 0) g_ri[j0 + b] = v;
        }
    }

    // ---- completion protocol: last block computes the final scalar ----
    __threadfence();
    if (tid == 0) done = atomicAdd(&g_ctr, 1);
    __syncthreads();
    if (done != GRID_PSD - 1) return;
    __threadfence();   // order: counter observation -> g_ri reads

    // Final reduction: pn = ca/max(ca); ||pn1-pn2||; 1/(l+eps)
    float m1 = 0.f, m2 = 0.f;
    for (int j = tid; j < K_BINS; j += BT) {
        float4 v = g_ri[j];
        float ca1 = __fmaf_rn(v.y, v.y, __fmul_rn(v.x, v.x));
        float ca2 = __fmaf_rn(v.w, v.w, __fmul_rn(v.z, v.z));
        ca1s[j] = ca1; ca2s[j] = ca2;
        m1 = fmaxf(m1, ca1); m2 = fmaxf(m2, ca2);
    }
    for (int off = 16; off; off >>= 1) {
        m1 = fmaxf(m1, __shfl_down_sync(msk, m1, off));
        m2 = fmaxf(m2, __shfl_down_sync(msk, m2, off));
    }
    if (lane == 0) { redf[w] = m1; redf[32 + w] = m2; }
    __syncthreads();
    if (tid == 0) {
        float a = redf[0], bb = redf[32];
        for (int i = 1; i < 8; i++) { a = fmaxf(a, redf[i]); bb = fmaxf(bb, redf[32 + i]); }
        redf[0] = a; redf[32] = bb;
    }
    __syncthreads();
    const float max1 = redf[0], max2 = redf[32];

    double ss = 0.0;
    for (int j = tid; j < K_BINS; j += BT) {
        float p1 = __fdiv_rn(ca1s[j], max1);
        float p2 = __fdiv_rn(ca2s[j], max2);
        double d = (double)p1 - (double)p2;
        ss += d * d;
    }
    for (int off = 16; off; off >>= 1) ss += __shfl_down_sync(msk, ss, off);
    if (lane == 0) redd[w] = ss;
    __syncthreads();
    if (tid == 0) {
        double tt = 0.0;
        for (int i = 0; i < 8; i++) tt += redd[i];
        float loss = (float)sqrt(tt);
        out[0] = __fdiv_rn(1.0f, loss + 1e-8f);
        g_ctr  = 0;    // reset for next graph replay
        g_pctr = 0;    // (runs after every block passed the prep barrier)
    }
}

// ---------------------------------------------------------------------------
// Inputs (metadata order): preds f32[60000], labels f32[60000], Fs i32[1],
//                          bpm_range f32[1400]. Output: f32[1].
// ---------------------------------------------------------------------------
extern "C" void kernel_launch(void* const* d_in, const int* in_sizes, int n_in,
                              void* d_out, int out_size) {
    const float* preds  = (const float*)d_in[0];
    const float* labels = (const float*)d_in[1];
    const float* bpm    = (const float*)d_in[3];

    psd_kernel<<<GRID_PSD, BT>>>(preds, labels, bpm, (float*)d_out);
}